// round 10
// baseline (speedup 1.0000x reference)
#include <cuda_runtime.h>
#include <cuda_fp16.h>
#include <math.h>
#include <stdint.h>

#define NB 64
#define H  1024
#define LQ 1024

__device__ float g_d[NB * H];
__device__ float g_scores[NB * LQ];
__device__ float g_ctx[NB * H];
__device__ __align__(128) __half g_enc_h[(size_t)NB * LQ * H];   // enc, fp16
__device__ __align__(128) __half g_W_h[H * H];                   // W_enc^T [d][k] fp16

// ---- smem layout for k_score_mma (dynamic) ----
#define SM_SSC   0
#define SM_GD    512
#define SM_WONE  4608
#define SM_BUF   8704
#define A_PITCH  80                       /* 32 fp16 = 64B + 16B pad: conflict-free ldmatrix */
#define ABUF_SZ  (128 * A_PITCH)          /* 10240 */
#define BBUF_SZ  (128 * A_PITCH)          /* 10240 */
#define BUF_SZ   (ABUF_SZ + BBUF_SZ)      /* 20480 */
#define NSTAGE   4
#define SMEM_TOTAL (SM_BUF + NSTAGE * BUF_SZ)  /* 90624 */

__device__ __forceinline__ uint32_t smem_u32(const void* p) {
    uint32_t a;
    asm("{ .reg .u64 t; cvta.to.shared.u64 t, %1; cvt.u32.u64 %0, t; }" : "=r"(a) : "l"(p));
    return a;
}
__device__ __forceinline__ void cpa16(uint32_t d, const void* s) {
    asm volatile("cp.async.cg.shared.global [%0], [%1], 16;" :: "r"(d), "l"(s));
}
__device__ __forceinline__ void ldm4(uint32_t* r, uint32_t a) {
    asm volatile("ldmatrix.sync.aligned.m8n8.x4.shared.b16 {%0,%1,%2,%3}, [%4];"
                 : "=r"(r[0]), "=r"(r[1]), "=r"(r[2]), "=r"(r[3]) : "r"(a));
}
__device__ __forceinline__ void mma_f16(float* c, const uint32_t* a, const uint32_t* b) {
    asm volatile("mma.sync.aligned.m16n8k16.row.col.f32.f16.f16.f32 "
                 "{%0,%1,%2,%3}, {%4,%5,%6,%7}, {%8,%9}, {%0,%1,%2,%3};"
                 : "+f"(c[0]), "+f"(c[1]), "+f"(c[2]), "+f"(c[3])
                 : "r"(a[0]), "r"(a[1]), "r"(a[2]), "r"(a[3]), "r"(b[0]), "r"(b[1]));
}

// ---------------- prep: enc fp32 -> fp16 ----------------
__global__ void k_prep_enc(const float4* __restrict__ enc4) {
    __half2* h2 = (__half2*)g_enc_h;
    size_t total = (size_t)NB * LQ * H / 4;
    for (size_t i = (size_t)blockIdx.x * blockDim.x + threadIdx.x; i < total;
         i += (size_t)gridDim.x * blockDim.x) {
        float4 v = enc4[i];
        h2[2 * i]     = __floats2half2_rn(v.x, v.y);
        h2[2 * i + 1] = __floats2half2_rn(v.z, v.w);
    }
}
// prep: W_enc[k][d] -> [d][k] fp16
__global__ void k_prep_w(const float* __restrict__ W) {
    __shared__ float t[32][33];
    int d0 = blockIdx.x * 32, k0 = blockIdx.y * 32;
    int tx = threadIdx.x, ty = threadIdx.y;  // (32,8)
    #pragma unroll
    for (int i = 0; i < 4; i++)
        t[ty + 8 * i][tx] = W[(k0 + ty + 8 * i) * H + d0 + tx];
    __syncthreads();
    #pragma unroll
    for (int i = 0; i < 4; i++) {
        float v = t[tx][ty + 8 * i];
        g_W_h[(size_t)(d0 + ty + 8 * i) * H + k0 + tx] = __float2half_rn(v);
    }
}

// ---------------- init ----------------
__global__ void k_init(const float* __restrict__ b_dec, const float* __restrict__ b_enc,
                       const float* __restrict__ b_att, float* __restrict__ out_h) {
    int n = blockIdx.x;
    for (int j = threadIdx.x; j < H; j += blockDim.x) {
        g_d[n * H + j]   = b_dec[j] + b_enc[j];
        g_ctx[n * H + j] = 0.f;
        out_h[n * H + j] = b_att[j];
    }
}

// ---------------- small fp32 gemm (64x1024 @ 1024x1024, split-K atomics) ----------------
__device__ __forceinline__ void gemm64_body(const float* __restrict__ A,
                                            const float* __restrict__ W,
                                            float* __restrict__ C) {
    __shared__ float As[64][17];
    __shared__ float Bs[16][64];
    int nt = blockIdx.x, ks = blockIdx.y, tid = threadIdx.x;
    int tx = tid & 15, ty = tid >> 4;
    float acc[4][4] = {};
    int k0end = ks * 256 + 256;
    for (int k0 = ks * 256; k0 < k0end; k0 += 16) {
        int ka = tid & 15, ma = tid >> 4;
        #pragma unroll
        for (int i = 0; i < 4; i++)
            As[ma + 16 * i][ka] = A[(ma + 16 * i) * H + k0 + ka];
        int jb = tid & 63, kb = tid >> 6;
        #pragma unroll
        for (int q = 0; q < 4; q++)
            Bs[kb + 4 * q][jb] = W[(k0 + kb + 4 * q) * H + nt * 64 + jb];
        __syncthreads();
        #pragma unroll
        for (int kk = 0; kk < 16; kk++) {
            float a[4], b[4];
            #pragma unroll
            for (int i = 0; i < 4; i++) a[i] = As[ty * 4 + i][kk];
            #pragma unroll
            for (int j = 0; j < 4; j++) b[j] = Bs[kk][tx * 4 + j];
            #pragma unroll
            for (int i = 0; i < 4; i++)
                #pragma unroll
                for (int j = 0; j < 4; j++)
                    acc[i][j] += a[i] * b[j];
        }
        __syncthreads();
    }
    #pragma unroll
    for (int i = 0; i < 4; i++)
        #pragma unroll
        for (int j = 0; j < 4; j++)
            atomicAdd(&C[(ty * 4 + i) * H + nt * 64 + tx * 4 + j], acc[i][j]);
}
__global__ void k_gemm64(const float* A, const float* W, float* C) {
    gemm64_body(A ? A : g_ctx, W, C);
}
__global__ void k_gemm64_to_gd(const float* A, const float* W) {
    gemm64_body(A, W, g_d);
}

// ---------------- HMMA fused score kernel (fp16, BK=32, 4-stage pipeline) ----------------
// scores[n,l] = sum_d Wone[d]*tanh(g_d[n,d] + (enc[n,l,:]@Wenc)[d])
// BM=128 l, BN=128 d-chunk (x8), BK=32 (32 k-tiles per chunk).
__device__ __forceinline__ void load_tile(uint32_t sb, int stage, int tid,
                                          int n, int l0, int cc, int kt) {
    uint32_t Ab = sb + SM_BUF + stage * BUF_SZ;
    uint32_t Bb = Ab + ABUF_SZ;
    #pragma unroll
    for (int i = 0; i < 2; i++) {
        int q = tid + 256 * i;          // 0..511
        int row = q >> 2, c = q & 3;    // 128 rows x 4 x 16B
        uint32_t doff = (uint32_t)(row * A_PITCH + c * 16);
        size_t sa = (size_t)(n * LQ + l0 + row) * H + kt * 32 + c * 8;
        cpa16(Ab + doff, g_enc_h + sa);
        size_t sbb = (size_t)(cc * 128 + row) * H + kt * 32 + c * 8;
        cpa16(Bb + doff, g_W_h + sbb);
    }
    asm volatile("cp.async.commit_group;" ::: "memory");
}

__global__ void __launch_bounds__(256, 2) k_score_mma(const float* __restrict__ Wone) {
    extern __shared__ char smem[];
    uint32_t sb = smem_u32(smem);
    int tid = threadIdx.x;
    int l0 = blockIdx.x * 128, n = blockIdx.y;

    float* sSC = (float*)(smem + SM_SSC);
    float* sGD = (float*)(smem + SM_GD);
    float* sWO = (float*)(smem + SM_WONE);
    if (tid < 128) sSC[tid] = 0.f;
    for (int j = tid; j < H; j += 256) { sGD[j] = g_d[n * H + j]; sWO[j] = Wone[j]; }

    int warp = tid >> 5, lane = tid & 31;
    int wm = warp & 3, wn = warp >> 2;           // 4 m-tiles x 2 n-tiles
    int g = lane >> 3, lr = lane & 7;
    int a_row = wm * 32 + (g & 1) * 8 + lr;      // + mf*16
    int a_kb  = (g >> 1) * 16;                   // + s*32 bytes
    int b_row = wn * 64 + (g >> 1) * 8 + lr;     // + p*16
    int b_kb  = (g & 1) * 16;                    // + s*32 bytes

    float acc[2][8][4] = {};

    // prologue: fill 3 stages
    load_tile(sb, 0, tid, n, l0, 0, 0);
    load_tile(sb, 1, tid, n, l0, 0, 1);
    load_tile(sb, 2, tid, n, l0, 0, 2);
    __syncthreads();

    for (int t = 0; t < 256; t++) {              // t = cc*32 + kt
        int stage = t & 3, cc = t >> 5, kt = t & 31;
        asm volatile("cp.async.wait_group 2;" ::: "memory");
        __syncthreads();                          // tile t visible; compute t-1 done
        if (t < 253) {
            int tn = t + 3;
            load_tile(sb, (t + 3) & 3, tid, n, l0, tn >> 5, tn & 31);
        }
        uint32_t Ab = sb + SM_BUF + stage * BUF_SZ;
        uint32_t Bb = Ab + ABUF_SZ;

        uint32_t a[2][2][4], b[2][8][2];
        // load s=0 into set 0
        #pragma unroll
        for (int mf = 0; mf < 2; mf++)
            ldm4(a[0][mf], Ab + (uint32_t)((a_row + mf * 16) * A_PITCH + a_kb));
        #pragma unroll
        for (int p = 0; p < 4; p++) {
            uint32_t r[4];
            ldm4(r, Bb + (uint32_t)((b_row + p * 16) * A_PITCH + b_kb));
            b[0][2 * p][0] = r[0]; b[0][2 * p][1] = r[1];
            b[0][2 * p + 1][0] = r[2]; b[0][2 * p + 1][1] = r[3];
        }
        #pragma unroll
        for (int s = 0; s < 2; s++) {
            int cur = s & 1, nxt = cur ^ 1;
            if (s < 1) {   // prefetch s=1 while MMAing s=0
                #pragma unroll
                for (int mf = 0; mf < 2; mf++)
                    ldm4(a[nxt][mf], Ab + (uint32_t)((a_row + mf * 16) * A_PITCH + a_kb + 32));
                #pragma unroll
                for (int p = 0; p < 4; p++) {
                    uint32_t r[4];
                    ldm4(r, Bb + (uint32_t)((b_row + p * 16) * A_PITCH + b_kb + 32));
                    b[nxt][2 * p][0] = r[0]; b[nxt][2 * p][1] = r[1];
                    b[nxt][2 * p + 1][0] = r[2]; b[nxt][2 * p + 1][1] = r[3];
                }
            }
            #pragma unroll
            for (int mf = 0; mf < 2; mf++)
                #pragma unroll
                for (int nf = 0; nf < 8; nf++)
                    mma_f16(acc[mf][nf], a[cur][mf], b[cur][nf]);
        }

        if (kt == 31) {
            // epilogue: acc == e[l, cc*128 .. +128)
            #pragma unroll
            for (int mf = 0; mf < 2; mf++) {
                float p0 = 0.f, p8 = 0.f;
                #pragma unroll
                for (int nf = 0; nf < 8; nf++) {
                    #pragma unroll
                    for (int i = 0; i < 2; i++) {
                        int d = cc * 128 + wn * 64 + nf * 8 + 2 * (lane & 3) + i;
                        float w = sWO[d], gd = sGD[d];
                        float t0, t8;
                        asm("tanh.approx.f32 %0, %1;" : "=f"(t0) : "f"(gd + acc[mf][nf][i]));
                        asm("tanh.approx.f32 %0, %1;" : "=f"(t8) : "f"(gd + acc[mf][nf][2 + i]));
                        p0 = fmaf(w, t0, p0);
                        p8 = fmaf(w, t8, p8);
                        acc[mf][nf][i] = 0.f;
                        acc[mf][nf][2 + i] = 0.f;
                    }
                }
                #pragma unroll
                for (int o = 1; o <= 2; o <<= 1) {
                    p0 += __shfl_xor_sync(~0u, p0, o);
                    p8 += __shfl_xor_sync(~0u, p8, o);
                }
                if ((lane & 3) == 0) {
                    int r = wm * 32 + mf * 16 + (lane >> 2);
                    atomicAdd(&sSC[r], p0);
                    atomicAdd(&sSC[r + 8], p8);
                }
            }
        }
    }
    __syncthreads();
    if (tid < 128) g_scores[n * LQ + l0 + tid] = sSC[tid];
}

// ---------------- softmax ----------------
__global__ void k_softmax(float* __restrict__ alpha_out) {
    __shared__ float rbuf[8];
    int n = blockIdx.x, tid = threadIdx.x;
    const float* s = g_scores + n * LQ;
    float v[4], mx = -1e30f;
    #pragma unroll
    for (int i = 0; i < 4; i++) { v[i] = s[tid + 256 * i]; mx = fmaxf(mx, v[i]); }
    #pragma unroll
    for (int o = 16; o > 0; o >>= 1) mx = fmaxf(mx, __shfl_xor_sync(~0u, mx, o));
    if ((tid & 31) == 0) rbuf[tid >> 5] = mx;
    __syncthreads();
    mx = rbuf[0];
    #pragma unroll
    for (int w = 1; w < 8; w++) mx = fmaxf(mx, rbuf[w]);
    __syncthreads();
    float e[4], sum = 0.f;
    #pragma unroll
    for (int i = 0; i < 4; i++) { e[i] = expf(v[i] - mx); sum += e[i]; }
    #pragma unroll
    for (int o = 16; o > 0; o >>= 1) sum += __shfl_xor_sync(~0u, sum, o);
    if ((tid & 31) == 0) rbuf[tid >> 5] = sum;
    __syncthreads();
    float tot = 0.f;
    #pragma unroll
    for (int w = 0; w < 8; w++) tot += rbuf[w];
    float inv = 1.f / tot;
    #pragma unroll
    for (int i = 0; i < 4; i++) alpha_out[n * LQ + tid + 256 * i] = e[i] * inv;
}

// ---------------- ctx: reads fp16 enc (halves HBM traffic) ----------------
__global__ void k_ctx(const float* __restrict__ alpha) {
    int ls = blockIdx.x, n = blockIdx.y, tid = threadIdx.x;
    const float* al = alpha + n * LQ + ls * 64;
    const uint4* base =
        (const uint4*)(g_enc_h + ((size_t)n * LQ + ls * 64) * H) + tid;  // 8 fp16 each
    float acc[8] = {};
    #pragma unroll 4
    for (int l = 0; l < 64; l++) {
        float a = al[l];
        uint4 v = base[l * (H / 8)];
        const __half2* h = (const __half2*)&v;
        #pragma unroll
        for (int j = 0; j < 4; j++) {
            float2 f = __half22float2(h[j]);
            acc[2 * j]     = fmaf(a, f.x, acc[2 * j]);
            acc[2 * j + 1] = fmaf(a, f.y, acc[2 * j + 1]);
        }
    }
    float* c = g_ctx + n * H + tid * 8;
    #pragma unroll
    for (int j = 0; j < 8; j++) atomicAdd(c + j, acc[j]);
}

// ---------------- launch ----------------
extern "C" void kernel_launch(void* const* d_in, const int* in_sizes, int n_in,
                              void* d_out, int out_size) {
    const float* dec_h = (const float*)d_in[0];
    const float* enc   = (const float*)d_in[1];
    const float* W_dec = (const float*)d_in[2];
    const float* b_dec = (const float*)d_in[3];
    const float* W_enc = (const float*)d_in[4];
    const float* b_enc = (const float*)d_in[5];
    const float* W_one = (const float*)d_in[6];
    const float* W_att = (const float*)d_in[8];
    const float* b_att = (const float*)d_in[9];

    float* out_h = (float*)d_out;
    float* alpha = (float*)d_out + NB * H;

    cudaFuncSetAttribute(k_score_mma, cudaFuncAttributeMaxDynamicSharedMemorySize, SMEM_TOTAL);

    k_init<<<NB, 256>>>(b_dec, b_enc, b_att, out_h);
    k_gemm64_to_gd<<<dim3(16, 4), 256>>>(dec_h, W_dec);
    k_prep_enc<<<1024, 256>>>((const float4*)enc);
    k_prep_w<<<dim3(32, 32), dim3(32, 8)>>>(W_enc);
    k_score_mma<<<dim3(8, NB), 256, SMEM_TOTAL>>>(W_one);
    k_softmax<<<NB, 256>>>(alpha);
    k_ctx<<<dim3(16, NB), 128>>>(alpha);
    k_gemm64<<<dim3(16, 4), 256>>>(nullptr, W_att, out_h);
}

// round 11
// speedup vs baseline: 1.2686x; 1.2686x over previous
#include <cuda_runtime.h>
#include <cuda_fp16.h>
#include <math.h>
#include <stdint.h>

#define NB 64
#define H  1024
#define LQ 1024

__device__ float g_d[NB * H];
__device__ float g_scores[NB * LQ];
__device__ float g_ctx[NB * H];
__device__ __align__(128) __half g_enc_h[(size_t)NB * LQ * H];   // enc, fp16
__device__ __align__(128) __half g_W_h[H * H];                   // W_enc^T [d][k] fp16

// ---- smem layout for k_score_mma (dynamic) ----
#define SM_SSC   0
#define SM_GD    512
#define SM_WONE  4608
#define SM_BUF   8704
#define ABUF_SZ  16384                    /* 128 rows x 128B, XOR-swizzled */
#define BBUF_SZ  16384
#define BUF_SZ   (ABUF_SZ + BBUF_SZ)      /* 32768 */
#define NSTAGE   3
#define SMEM_TOTAL (SM_BUF + NSTAGE * BUF_SZ)  /* 107008 -> 2 CTAs/SM */

__device__ __forceinline__ uint32_t smem_u32(const void* p) {
    uint32_t a;
    asm("{ .reg .u64 t; cvta.to.shared.u64 t, %1; cvt.u32.u64 %0, t; }" : "=r"(a) : "l"(p));
    return a;
}
__device__ __forceinline__ void cpa16(uint32_t d, const void* s) {
    asm volatile("cp.async.cg.shared.global [%0], [%1], 16;" :: "r"(d), "l"(s));
}
__device__ __forceinline__ void ldm4(uint32_t* r, uint32_t a) {
    asm volatile("ldmatrix.sync.aligned.m8n8.x4.shared.b16 {%0,%1,%2,%3}, [%4];"
                 : "=r"(r[0]), "=r"(r[1]), "=r"(r[2]), "=r"(r[3]) : "r"(a));
}
__device__ __forceinline__ void mma_f16(float* c, const uint32_t* a, const uint32_t* b) {
    asm volatile("mma.sync.aligned.m16n8k16.row.col.f32.f16.f16.f32 "
                 "{%0,%1,%2,%3}, {%4,%5,%6,%7}, {%8,%9}, {%0,%1,%2,%3};"
                 : "+f"(c[0]), "+f"(c[1]), "+f"(c[2]), "+f"(c[3])
                 : "r"(a[0]), "r"(a[1]), "r"(a[2]), "r"(a[3]), "r"(b[0]), "r"(b[1]));
}

// ---------------- prep: enc fp32 -> fp16 ----------------
__global__ void k_prep_enc(const float4* __restrict__ enc4) {
    __half2* h2 = (__half2*)g_enc_h;
    size_t total = (size_t)NB * LQ * H / 4;
    for (size_t i = (size_t)blockIdx.x * blockDim.x + threadIdx.x; i < total;
         i += (size_t)gridDim.x * blockDim.x) {
        float4 v = enc4[i];
        h2[2 * i]     = __floats2half2_rn(v.x, v.y);
        h2[2 * i + 1] = __floats2half2_rn(v.z, v.w);
    }
}
// prep: W_enc[k][d] -> [d][k] fp16
__global__ void k_prep_w(const float* __restrict__ W) {
    __shared__ float t[32][33];
    int d0 = blockIdx.x * 32, k0 = blockIdx.y * 32;
    int tx = threadIdx.x, ty = threadIdx.y;  // (32,8)
    #pragma unroll
    for (int i = 0; i < 4; i++)
        t[ty + 8 * i][tx] = W[(k0 + ty + 8 * i) * H + d0 + tx];
    __syncthreads();
    #pragma unroll
    for (int i = 0; i < 4; i++) {
        float v = t[tx][ty + 8 * i];
        g_W_h[(size_t)(d0 + ty + 8 * i) * H + k0 + tx] = __float2half_rn(v);
    }
}

// ---------------- init ----------------
__global__ void k_init(const float* __restrict__ b_dec, const float* __restrict__ b_enc,
                       const float* __restrict__ b_att, float* __restrict__ out_h) {
    int n = blockIdx.x;
    for (int j = threadIdx.x; j < H; j += blockDim.x) {
        g_d[n * H + j]   = b_dec[j] + b_enc[j];
        g_ctx[n * H + j] = 0.f;
        out_h[n * H + j] = b_att[j];
    }
}

// ---------------- small fp32 gemm (64x1024 @ 1024x1024, split-K atomics) ----------------
__device__ __forceinline__ void gemm64_body(const float* __restrict__ A,
                                            const float* __restrict__ W,
                                            float* __restrict__ C) {
    __shared__ float As[64][17];
    __shared__ float Bs[16][64];
    int nt = blockIdx.x, ks = blockIdx.y, tid = threadIdx.x;
    int tx = tid & 15, ty = tid >> 4;
    float acc[4][4] = {};
    int k0end = ks * 256 + 256;
    for (int k0 = ks * 256; k0 < k0end; k0 += 16) {
        int ka = tid & 15, ma = tid >> 4;
        #pragma unroll
        for (int i = 0; i < 4; i++)
            As[ma + 16 * i][ka] = A[(ma + 16 * i) * H + k0 + ka];
        int jb = tid & 63, kb = tid >> 6;
        #pragma unroll
        for (int q = 0; q < 4; q++)
            Bs[kb + 4 * q][jb] = W[(k0 + kb + 4 * q) * H + nt * 64 + jb];
        __syncthreads();
        #pragma unroll
        for (int kk = 0; kk < 16; kk++) {
            float a[4], b[4];
            #pragma unroll
            for (int i = 0; i < 4; i++) a[i] = As[ty * 4 + i][kk];
            #pragma unroll
            for (int j = 0; j < 4; j++) b[j] = Bs[kk][tx * 4 + j];
            #pragma unroll
            for (int i = 0; i < 4; i++)
                #pragma unroll
                for (int j = 0; j < 4; j++)
                    acc[i][j] += a[i] * b[j];
        }
        __syncthreads();
    }
    #pragma unroll
    for (int i = 0; i < 4; i++)
        #pragma unroll
        for (int j = 0; j < 4; j++)
            atomicAdd(&C[(ty * 4 + i) * H + nt * 64 + tx * 4 + j], acc[i][j]);
}
__global__ void k_gemm64(const float* A, const float* W, float* C) {
    gemm64_body(A ? A : g_ctx, W, C);
}
__global__ void k_gemm64_to_gd(const float* A, const float* W) {
    gemm64_body(A, W, g_d);
}

// ---------------- HMMA fused score kernel (fp16, BK=64, 3-stage, XOR swizzle) ------------
// scores[n,l] = sum_d Wone[d]*tanh(g_d[n,d] + (enc[n,l,:]@Wenc)[d])
// BM=128 l, BN=128 d-chunk (x8), BK=64 (16 k-tiles per chunk, 128 tiles total).
// smem row: 128B = 8 x 16B chunks, chunk stored at (c ^ (row&7)).
__device__ __forceinline__ void load_tile(uint32_t sb, int stage, int tid,
                                          int n, int l0, int cc, int kt) {
    uint32_t Ab = sb + SM_BUF + stage * BUF_SZ;
    uint32_t Bb = Ab + ABUF_SZ;
    #pragma unroll
    for (int i = 0; i < 4; i++) {
        int q = tid + 256 * i;          // 0..1023
        int row = q >> 3, c = q & 7;
        uint32_t doff = ((uint32_t)row << 7) + (uint32_t)((c ^ (row & 7)) << 4);
        size_t sa = (size_t)(n * LQ + l0 + row) * H + kt * 64 + c * 8;
        cpa16(Ab + doff, g_enc_h + sa);
        size_t sbb = (size_t)(cc * 128 + row) * H + kt * 64 + c * 8;
        cpa16(Bb + doff, g_W_h + sbb);
    }
    asm volatile("cp.async.commit_group;" ::: "memory");
}

__global__ void __launch_bounds__(256, 2) k_score_mma(const float* __restrict__ Wone) {
    extern __shared__ char smem[];
    uint32_t sb = smem_u32(smem);
    int tid = threadIdx.x;
    int l0 = blockIdx.x * 128, n = blockIdx.y;

    float* sSC = (float*)(smem + SM_SSC);
    float* sGD = (float*)(smem + SM_GD);
    float* sWO = (float*)(smem + SM_WONE);
    if (tid < 128) sSC[tid] = 0.f;
    for (int j = tid; j < H; j += 256) { sGD[j] = g_d[n * H + j]; sWO[j] = Wone[j]; }

    int warp = tid >> 5, lane = tid & 31;
    int wm = warp & 3, wn = warp >> 2;           // 4 m-tiles x 2 n-tiles
    int g = lane >> 3, lr = lane & 7;
    int a_row = wm * 32 + (g & 1) * 8 + lr;      // + mf*16
    int a_kc0 = (g >> 1);                        // 16B-chunk idx; + 2*s
    int b_row = wn * 64 + (g >> 1) * 8 + lr;     // + p*16
    int b_kc0 = (g & 1);                         // + 2*s
    uint32_t rxa = (uint32_t)(a_row & 7), rxb = (uint32_t)(b_row & 7);
    uint32_t roa[2], rob[4];
    #pragma unroll
    for (int mf = 0; mf < 2; mf++) roa[mf] = (uint32_t)((a_row + mf * 16) << 7);
    #pragma unroll
    for (int p = 0; p < 4; p++)  rob[p] = (uint32_t)((b_row + p * 16) << 7);

    float acc[2][8][4] = {};

    // prologue: fill 2 stages
    load_tile(sb, 0, tid, n, l0, 0, 0);
    load_tile(sb, 1, tid, n, l0, 0, 1);

    for (int t = 0; t < 128; t++) {              // t = cc*16 + kt
        int stage = t % 3, cc = t >> 4, kt = t & 15;
        if (t < 127) { asm volatile("cp.async.wait_group 1;" ::: "memory"); }
        else         { asm volatile("cp.async.wait_group 0;" ::: "memory"); }
        __syncthreads();                          // tile t visible; stage (t+2)%3 free
        if (t < 126) {
            int tn = t + 2;
            load_tile(sb, (t + 2) % 3, tid, n, l0, tn >> 4, tn & 15);
        }
        uint32_t Ab = sb + SM_BUF + stage * BUF_SZ;
        uint32_t Bb = Ab + ABUF_SZ;

        uint32_t a[2][2][4], b[2][8][2];
        // load s=0 into set 0
        #pragma unroll
        for (int mf = 0; mf < 2; mf++)
            ldm4(a[0][mf], Ab + roa[mf] + ((((uint32_t)a_kc0) ^ rxa) << 4));
        #pragma unroll
        for (int p = 0; p < 4; p++) {
            uint32_t r[4];
            ldm4(r, Bb + rob[p] + ((((uint32_t)b_kc0) ^ rxb) << 4));
            b[0][2 * p][0] = r[0]; b[0][2 * p][1] = r[1];
            b[0][2 * p + 1][0] = r[2]; b[0][2 * p + 1][1] = r[3];
        }
        #pragma unroll
        for (int s = 0; s < 4; s++) {
            int cur = s & 1, nxt = cur ^ 1;
            if (s < 3) {   // prefetch s+1 while MMAing s
                uint32_t kca = (uint32_t)(a_kc0 + 2 * (s + 1));
                uint32_t kcb = (uint32_t)(b_kc0 + 2 * (s + 1));
                #pragma unroll
                for (int mf = 0; mf < 2; mf++)
                    ldm4(a[nxt][mf], Ab + roa[mf] + ((kca ^ rxa) << 4));
                #pragma unroll
                for (int p = 0; p < 4; p++) {
                    uint32_t r[4];
                    ldm4(r, Bb + rob[p] + ((kcb ^ rxb) << 4));
                    b[nxt][2 * p][0] = r[0]; b[nxt][2 * p][1] = r[1];
                    b[nxt][2 * p + 1][0] = r[2]; b[nxt][2 * p + 1][1] = r[3];
                }
            }
            #pragma unroll
            for (int mf = 0; mf < 2; mf++)
                #pragma unroll
                for (int nf = 0; nf < 8; nf++)
                    mma_f16(acc[mf][nf], a[cur][mf], b[cur][nf]);
        }

        if (kt == 15) {
            // epilogue: acc == e[l, cc*128 .. +128)
            #pragma unroll
            for (int mf = 0; mf < 2; mf++) {
                float p0 = 0.f, p8 = 0.f;
                #pragma unroll
                for (int nf = 0; nf < 8; nf++) {
                    #pragma unroll
                    for (int i = 0; i < 2; i++) {
                        int d = cc * 128 + wn * 64 + nf * 8 + 2 * (lane & 3) + i;
                        float w = sWO[d], gd = sGD[d];
                        float t0, t8;
                        asm("tanh.approx.f32 %0, %1;" : "=f"(t0) : "f"(gd + acc[mf][nf][i]));
                        asm("tanh.approx.f32 %0, %1;" : "=f"(t8) : "f"(gd + acc[mf][nf][2 + i]));
                        p0 = fmaf(w, t0, p0);
                        p8 = fmaf(w, t8, p8);
                        acc[mf][nf][i] = 0.f;
                        acc[mf][nf][2 + i] = 0.f;
                    }
                }
                #pragma unroll
                for (int o = 1; o <= 2; o <<= 1) {
                    p0 += __shfl_xor_sync(~0u, p0, o);
                    p8 += __shfl_xor_sync(~0u, p8, o);
                }
                if ((lane & 3) == 0) {
                    int r = wm * 32 + mf * 16 + (lane >> 2);
                    atomicAdd(&sSC[r], p0);
                    atomicAdd(&sSC[r + 8], p8);
                }
            }
        }
    }
    __syncthreads();
    if (tid < 128) g_scores[n * LQ + l0 + tid] = sSC[tid];
}

// ---------------- softmax ----------------
__global__ void k_softmax(float* __restrict__ alpha_out) {
    __shared__ float rbuf[8];
    int n = blockIdx.x, tid = threadIdx.x;
    const float* s = g_scores + n * LQ;
    float v[4], mx = -1e30f;
    #pragma unroll
    for (int i = 0; i < 4; i++) { v[i] = s[tid + 256 * i]; mx = fmaxf(mx, v[i]); }
    #pragma unroll
    for (int o = 16; o > 0; o >>= 1) mx = fmaxf(mx, __shfl_xor_sync(~0u, mx, o));
    if ((tid & 31) == 0) rbuf[tid >> 5] = mx;
    __syncthreads();
    mx = rbuf[0];
    #pragma unroll
    for (int w = 1; w < 8; w++) mx = fmaxf(mx, rbuf[w]);
    __syncthreads();
    float e[4], sum = 0.f;
    #pragma unroll
    for (int i = 0; i < 4; i++) { e[i] = expf(v[i] - mx); sum += e[i]; }
    #pragma unroll
    for (int o = 16; o > 0; o >>= 1) sum += __shfl_xor_sync(~0u, sum, o);
    if ((tid & 31) == 0) rbuf[tid >> 5] = sum;
    __syncthreads();
    float tot = 0.f;
    #pragma unroll
    for (int w = 0; w < 8; w++) tot += rbuf[w];
    float inv = 1.f / tot;
    #pragma unroll
    for (int i = 0; i < 4; i++) alpha_out[n * LQ + tid + 256 * i] = e[i] * inv;
}

// ---------------- ctx: reads fp16 enc ----------------
__global__ void k_ctx(const float* __restrict__ alpha) {
    int ls = blockIdx.x, n = blockIdx.y, tid = threadIdx.x;
    const float* al = alpha + n * LQ + ls * 64;
    const uint4* base =
        (const uint4*)(g_enc_h + ((size_t)n * LQ + ls * 64) * H) + tid;  // 8 fp16 each
    float acc[8] = {};
    #pragma unroll 4
    for (int l = 0; l < 64; l++) {
        float a = al[l];
        uint4 v = base[l * (H / 8)];
        const __half2* h = (const __half2*)&v;
        #pragma unroll
        for (int j = 0; j < 4; j++) {
            float2 f = __half22float2(h[j]);
            acc[2 * j]     = fmaf(a, f.x, acc[2 * j]);
            acc[2 * j + 1] = fmaf(a, f.y, acc[2 * j + 1]);
        }
    }
    float* c = g_ctx + n * H + tid * 8;
    #pragma unroll
    for (int j = 0; j < 8; j++) atomicAdd(c + j, acc[j]);
}

// ---------------- launch ----------------
extern "C" void kernel_launch(void* const* d_in, const int* in_sizes, int n_in,
                              void* d_out, int out_size) {
    const float* dec_h = (const float*)d_in[0];
    const float* enc   = (const float*)d_in[1];
    const float* W_dec = (const float*)d_in[2];
    const float* b_dec = (const float*)d_in[3];
    const float* W_enc = (const float*)d_in[4];
    const float* b_enc = (const float*)d_in[5];
    const float* W_one = (const float*)d_in[6];
    const float* W_att = (const float*)d_in[8];
    const float* b_att = (const float*)d_in[9];

    float* out_h = (float*)d_out;
    float* alpha = (float*)d_out + NB * H;

    cudaFuncSetAttribute(k_score_mma, cudaFuncAttributeMaxDynamicSharedMemorySize, SMEM_TOTAL);

    k_init<<<NB, 256>>>(b_dec, b_enc, b_att, out_h);
    k_gemm64_to_gd<<<dim3(16, 4), 256>>>(dec_h, W_dec);
    k_prep_enc<<<1024, 256>>>((const float4*)enc);
    k_prep_w<<<dim3(32, 32), dim3(32, 8)>>>(W_enc);
    k_score_mma<<<dim3(8, NB), 256, SMEM_TOTAL>>>(W_one);
    k_softmax<<<NB, 256>>>(alpha);
    k_ctx<<<dim3(16, NB), 128>>>(alpha);
    k_gemm64<<<dim3(16, 4), 256>>>(nullptr, W_att, out_h);
}

// round 16
// speedup vs baseline: 1.2891x; 1.0161x over previous
#include <cuda_runtime.h>
#include <cuda_fp16.h>
#include <math.h>
#include <stdint.h>

#define NB 64
#define H  1024
#define LQ 1024

__device__ float g_d[NB * H];
__device__ float g_scores[NB * LQ];
__device__ float g_ctx[NB * H];
__device__ __align__(128) __half g_enc_h[(size_t)NB * LQ * H];   // enc, fp16
__device__ __align__(128) __half g_W_h[H * H];                   // W_enc^T [d][k] fp16

// ---- smem layout for k_score_mma (dynamic) ----
#define SM_SSC   0
#define SM_GD    512
#define SM_WONE  4608
#define SM_BUF   8704
#define ABUF_SZ  16384                    /* 128 rows x 128B, XOR-swizzled */
#define BBUF_SZ  16384
#define BUF_SZ   (ABUF_SZ + BBUF_SZ)      /* 32768 */
#define NSTAGE   3
#define SMEM_TOTAL (SM_BUF + NSTAGE * BUF_SZ)  /* 107008 -> 2 CTAs/SM */

__device__ __forceinline__ uint32_t smem_u32(const void* p) {
    uint32_t a;
    asm("{ .reg .u64 t; cvta.to.shared.u64 t, %1; cvt.u32.u64 %0, t; }" : "=r"(a) : "l"(p));
    return a;
}
__device__ __forceinline__ void cpa16(uint32_t d, const void* s) {
    asm volatile("cp.async.cg.shared.global [%0], [%1], 16;" :: "r"(d), "l"(s));
}
__device__ __forceinline__ void ldm4(uint32_t* r, uint32_t a) {
    asm volatile("ldmatrix.sync.aligned.m8n8.x4.shared.b16 {%0,%1,%2,%3}, [%4];"
                 : "=r"(r[0]), "=r"(r[1]), "=r"(r[2]), "=r"(r[3]) : "r"(a));
}
__device__ __forceinline__ void mma_f16(float* c, const uint32_t* a, const uint32_t* b) {
    asm volatile("mma.sync.aligned.m16n8k16.row.col.f32.f16.f16.f32 "
                 "{%0,%1,%2,%3}, {%4,%5,%6,%7}, {%8,%9}, {%0,%1,%2,%3};"
                 : "+f"(c[0]), "+f"(c[1]), "+f"(c[2]), "+f"(c[3])
                 : "r"(a[0]), "r"(a[1]), "r"(a[2]), "r"(a[3]), "r"(b[0]), "r"(b[1]));
}

// ---------------- prep: enc fp32 -> fp16 ----------------
__global__ void k_prep_enc(const float4* __restrict__ enc4) {
    __half2* h2 = (__half2*)g_enc_h;
    size_t total = (size_t)NB * LQ * H / 4;
    for (size_t i = (size_t)blockIdx.x * blockDim.x + threadIdx.x; i < total;
         i += (size_t)gridDim.x * blockDim.x) {
        float4 v = enc4[i];
        h2[2 * i]     = __floats2half2_rn(v.x, v.y);
        h2[2 * i + 1] = __floats2half2_rn(v.z, v.w);
    }
}
// prep: W_enc[k][d] -> [d][k] fp16
__global__ void k_prep_w(const float* __restrict__ W) {
    __shared__ float t[32][33];
    int d0 = blockIdx.x * 32, k0 = blockIdx.y * 32;
    int tx = threadIdx.x, ty = threadIdx.y;  // (32,8)
    #pragma unroll
    for (int i = 0; i < 4; i++)
        t[ty + 8 * i][tx] = W[(k0 + ty + 8 * i) * H + d0 + tx];
    __syncthreads();
    #pragma unroll
    for (int i = 0; i < 4; i++) {
        float v = t[tx][ty + 8 * i];
        g_W_h[(size_t)(d0 + ty + 8 * i) * H + k0 + tx] = __float2half_rn(v);
    }
}

// ---------------- init ----------------
__global__ void k_init(const float* __restrict__ b_dec, const float* __restrict__ b_enc,
                       const float* __restrict__ b_att, float* __restrict__ out_h) {
    int n = blockIdx.x;
    for (int j = threadIdx.x; j < H; j += blockDim.x) {
        g_d[n * H + j]   = b_dec[j] + b_enc[j];
        g_ctx[n * H + j] = 0.f;
        out_h[n * H + j] = b_att[j];
    }
}

// ---------------- small fp32 gemm (64x1024 @ 1024x1024, split-K atomics) ----------------
__device__ __forceinline__ void gemm64_body(const float* __restrict__ A,
                                            const float* __restrict__ W,
                                            float* __restrict__ C) {
    __shared__ float As[64][17];
    __shared__ float Bs[16][64];
    int nt = blockIdx.x, ks = blockIdx.y, tid = threadIdx.x;
    int tx = tid & 15, ty = tid >> 4;
    float acc[4][4] = {};
    int k0end = ks * 256 + 256;
    for (int k0 = ks * 256; k0 < k0end; k0 += 16) {
        int ka = tid & 15, ma = tid >> 4;
        #pragma unroll
        for (int i = 0; i < 4; i++)
            As[ma + 16 * i][ka] = A[(ma + 16 * i) * H + k0 + ka];
        int jb = tid & 63, kb = tid >> 6;
        #pragma unroll
        for (int q = 0; q < 4; q++)
            Bs[kb + 4 * q][jb] = W[(k0 + kb + 4 * q) * H + nt * 64 + jb];
        __syncthreads();
        #pragma unroll
        for (int kk = 0; kk < 16; kk++) {
            float a[4], b[4];
            #pragma unroll
            for (int i = 0; i < 4; i++) a[i] = As[ty * 4 + i][kk];
            #pragma unroll
            for (int j = 0; j < 4; j++) b[j] = Bs[kk][tx * 4 + j];
            #pragma unroll
            for (int i = 0; i < 4; i++)
                #pragma unroll
                for (int j = 0; j < 4; j++)
                    acc[i][j] += a[i] * b[j];
        }
        __syncthreads();
    }
    #pragma unroll
    for (int i = 0; i < 4; i++)
        #pragma unroll
        for (int j = 0; j < 4; j++)
            atomicAdd(&C[(ty * 4 + i) * H + nt * 64 + tx * 4 + j], acc[i][j]);
}
__global__ void k_gemm64(const float* A, const float* W, float* C) {
    gemm64_body(A ? A : g_ctx, W, C);
}
__global__ void k_gemm64_to_gd(const float* A, const float* W) {
    gemm64_body(A, W, g_d);
}

// ---------------- HMMA fused score kernel (fp16, BK=64, 3-stage, 4 warps 64x64) --------
// scores[n,l] = sum_d Wone[d]*tanh(g_d[n,d] + (enc[n,l,:]@Wenc)[d])
// BM=128 l, BN=128 d-chunk (x8), BK=64 (16 k-tiles per chunk, 128 tiles total).
// 4 warps, warp tile 64x64: dup_A=dup_B=2 -> minimal LDSM issue pressure.
// smem row: 128B = 8 x 16B chunks, chunk stored at (c ^ (row&7)).
__device__ __forceinline__ void load_tile(uint32_t sb, int stage, int tid,
                                          int n, int l0, int cc, int kt) {
    uint32_t Ab = sb + SM_BUF + stage * BUF_SZ;
    uint32_t Bb = Ab + ABUF_SZ;
    #pragma unroll
    for (int i = 0; i < 8; i++) {
        int q = tid + 128 * i;          // 0..1023
        int row = q >> 3, c = q & 7;
        uint32_t doff = ((uint32_t)row << 7) + (uint32_t)((c ^ (row & 7)) << 4);
        size_t sa = (size_t)(n * LQ + l0 + row) * H + kt * 64 + c * 8;
        cpa16(Ab + doff, g_enc_h + sa);
        size_t sbb = (size_t)(cc * 128 + row) * H + kt * 64 + c * 8;
        cpa16(Bb + doff, g_W_h + sbb);
    }
    asm volatile("cp.async.commit_group;" ::: "memory");
}

__global__ void __launch_bounds__(128, 2) k_score_mma(const float* __restrict__ Wone) {
    extern __shared__ char smem[];
    uint32_t sb = smem_u32(smem);
    int tid = threadIdx.x;
    int l0 = blockIdx.x * 128, n = blockIdx.y;

    float* sSC = (float*)(smem + SM_SSC);
    float* sGD = (float*)(smem + SM_GD);
    float* sWO = (float*)(smem + SM_WONE);
    sSC[tid] = 0.f;
    for (int j = tid; j < H; j += 128) { sGD[j] = g_d[n * H + j]; sWO[j] = Wone[j]; }

    int warp = tid >> 5, lane = tid & 31;
    int wm = warp & 1, wn = warp >> 1;           // 2 m-tiles x 2 n-tiles (64x64 each)
    int g = lane >> 3, lr = lane & 7;
    int a_kc0 = (g >> 1);                        // 16B-chunk idx; + 2*s
    int b_kc0 = (g & 1);                         // + 2*s
    uint32_t roa[4], rob[4];
    uint32_t rxa[4], rxb[4];
    #pragma unroll
    for (int mf = 0; mf < 4; mf++) {
        int row = wm * 64 + mf * 16 + (g & 1) * 8 + lr;
        roa[mf] = (uint32_t)(row << 7);
        rxa[mf] = (uint32_t)(row & 7);
    }
    #pragma unroll
    for (int p = 0; p < 4; p++) {
        int row = wn * 64 + p * 16 + (g >> 1) * 8 + lr;
        rob[p] = (uint32_t)(row << 7);
        rxb[p] = (uint32_t)(row & 7);
    }

    float acc[4][8][4] = {};

    // prologue: fill 2 stages
    load_tile(sb, 0, tid, n, l0, 0, 0);
    load_tile(sb, 1, tid, n, l0, 0, 1);

    for (int t = 0; t < 128; t++) {              // t = cc*16 + kt
        int stage = t % 3, cc = t >> 4, kt = t & 15;
        if (t < 127) { asm volatile("cp.async.wait_group 1;" ::: "memory"); }
        else         { asm volatile("cp.async.wait_group 0;" ::: "memory"); }
        __syncthreads();                          // tile t visible; stage (t+2)%3 free
        if (t < 126) {
            int tn = t + 2;
            load_tile(sb, (t + 2) % 3, tid, n, l0, tn >> 4, tn & 15);
        }
        uint32_t Ab = sb + SM_BUF + stage * BUF_SZ;
        uint32_t Bb = Ab + ABUF_SZ;

        #pragma unroll
        for (int s = 0; s < 4; s++) {
            uint32_t a[4][4], b[8][2];
            uint32_t kca = (uint32_t)(a_kc0 + 2 * s);
            uint32_t kcb = (uint32_t)(b_kc0 + 2 * s);
            #pragma unroll
            for (int mf = 0; mf < 4; mf++)
                ldm4(a[mf], Ab + roa[mf] + ((kca ^ rxa[mf]) << 4));
            #pragma unroll
            for (int p = 0; p < 4; p++) {
                uint32_t r[4];
                ldm4(r, Bb + rob[p] + ((kcb ^ rxb[p]) << 4));
                b[2 * p][0] = r[0]; b[2 * p][1] = r[1];
                b[2 * p + 1][0] = r[2]; b[2 * p + 1][1] = r[3];
            }
            #pragma unroll
            for (int mf = 0; mf < 4; mf++)
                #pragma unroll
                for (int nf = 0; nf < 8; nf++)
                    mma_f16(acc[mf][nf], a[mf], b[nf]);
        }

        if (kt == 15) {
            // epilogue: acc == e[l, cc*128 .. +128)
            #pragma unroll
            for (int mf = 0; mf < 4; mf++) {
                float p0 = 0.f, p8 = 0.f;
                #pragma unroll
                for (int nf = 0; nf < 8; nf++) {
                    #pragma unroll
                    for (int i = 0; i < 2; i++) {
                        int d = cc * 128 + wn * 64 + nf * 8 + 2 * (lane & 3) + i;
                        float w = sWO[d], gd = sGD[d];
                        float t0, t8;
                        asm("tanh.approx.f32 %0, %1;" : "=f"(t0) : "f"(gd + acc[mf][nf][i]));
                        asm("tanh.approx.f32 %0, %1;" : "=f"(t8) : "f"(gd + acc[mf][nf][2 + i]));
                        p0 = fmaf(w, t0, p0);
                        p8 = fmaf(w, t8, p8);
                        acc[mf][nf][i] = 0.f;
                        acc[mf][nf][2 + i] = 0.f;
                    }
                }
                #pragma unroll
                for (int o = 1; o <= 2; o <<= 1) {
                    p0 += __shfl_xor_sync(~0u, p0, o);
                    p8 += __shfl_xor_sync(~0u, p8, o);
                }
                if ((lane & 3) == 0) {
                    int r = wm * 64 + mf * 16 + (lane >> 2);
                    atomicAdd(&sSC[r], p0);
                    atomicAdd(&sSC[r + 8], p8);
                }
            }
        }
    }
    __syncthreads();
    g_scores[n * LQ + l0 + tid] = sSC[tid];
}

// ---------------- softmax ----------------
__global__ void k_softmax(float* __restrict__ alpha_out) {
    __shared__ float rbuf[8];
    int n = blockIdx.x, tid = threadIdx.x;
    const float* s = g_scores + n * LQ;
    float v[4], mx = -1e30f;
    #pragma unroll
    for (int i = 0; i < 4; i++) { v[i] = s[tid + 256 * i]; mx = fmaxf(mx, v[i]); }
    #pragma unroll
    for (int o = 16; o > 0; o >>= 1) mx = fmaxf(mx, __shfl_xor_sync(~0u, mx, o));
    if ((tid & 31) == 0) rbuf[tid >> 5] = mx;
    __syncthreads();
    mx = rbuf[0];
    #pragma unroll
    for (int w = 1; w < 8; w++) mx = fmaxf(mx, rbuf[w]);
    __syncthreads();
    float e[4], sum = 0.f;
    #pragma unroll
    for (int i = 0; i < 4; i++) { e[i] = expf(v[i] - mx); sum += e[i]; }
    #pragma unroll
    for (int o = 16; o > 0; o >>= 1) sum += __shfl_xor_sync(~0u, sum, o);
    if ((tid & 31) == 0) rbuf[tid >> 5] = sum;
    __syncthreads();
    float tot = 0.f;
    #pragma unroll
    for (int w = 0; w < 8; w++) tot += rbuf[w];
    float inv = 1.f / tot;
    #pragma unroll
    for (int i = 0; i < 4; i++) alpha_out[n * LQ + tid + 256 * i] = e[i] * inv;
}

// ---------------- ctx: reads fp16 enc ----------------
__global__ void k_ctx(const float* __restrict__ alpha) {
    int ls = blockIdx.x, n = blockIdx.y, tid = threadIdx.x;
    const float* al = alpha + n * LQ + ls * 64;
    const uint4* base =
        (const uint4*)(g_enc_h + ((size_t)n * LQ + ls * 64) * H) + tid;  // 8 fp16 each
    float acc[8] = {};
    #pragma unroll 4
    for (int l = 0; l < 64; l++) {
        float a = al[l];
        uint4 v = base[l * (H / 8)];
        const __half2* h = (const __half2*)&v;
        #pragma unroll
        for (int j = 0; j < 4; j++) {
            float2 f = __half22float2(h[j]);
            acc[2 * j]     = fmaf(a, f.x, acc[2 * j]);
            acc[2 * j + 1] = fmaf(a, f.y, acc[2 * j + 1]);
        }
    }
    float* c = g_ctx + n * H + tid * 8;
    #pragma unroll
    for (int j = 0; j < 8; j++) atomicAdd(c + j, acc[j]);
}

// ---------------- launch ----------------
extern "C" void kernel_launch(void* const* d_in, const int* in_sizes, int n_in,
                              void* d_out, int out_size) {
    const float* dec_h = (const float*)d_in[0];
    const float* enc   = (const float*)d_in[1];
    const float* W_dec = (const float*)d_in[2];
    const float* b_dec = (const float*)d_in[3];
    const float* W_enc = (const float*)d_in[4];
    const float* b_enc = (const float*)d_in[5];
    const float* W_one = (const float*)d_in[6];
    const float* W_att = (const float*)d_in[8];
    const float* b_att = (const float*)d_in[9];

    float* out_h = (float*)d_out;
    float* alpha = (float*)d_out + NB * H;

    cudaFuncSetAttribute(k_score_mma, cudaFuncAttributeMaxDynamicSharedMemorySize, SMEM_TOTAL);

    k_init<<<NB, 256>>>(b_dec, b_enc, b_att, out_h);
    k_gemm64_to_gd<<<dim3(16, 4), 256>>>(dec_h, W_dec);
    k_prep_enc<<<1024, 256>>>((const float4*)enc);
    k_prep_w<<<dim3(32, 32), dim3(32, 8)>>>(W_enc);
    k_score_mma<<<dim3(8, NB), 128, SMEM_TOTAL>>>(W_one);
    k_softmax<<<NB, 256>>>(alpha);
    k_ctx<<<dim3(16, NB), 128>>>(alpha);
    k_gemm64<<<dim3(16, 4), 256>>>(nullptr, W_att, out_h);
}